// round 2
// baseline (speedup 1.0000x reference)
#include <cuda_runtime.h>

#define Nn 64
#define Cc 64
#define Tt 300
#define Vv 25
#define Ssub 3
#define Ichan 16
#define TV 7500
#define ITK 4800

// -------- scratch (device globals: no allocation allowed) --------
__device__ float g_ab[(size_t)Nn * 96 * TV];      // [n][96 rows: 0-47 = a(s,i), 48-95 = b(s,i)][t*25+v]
__device__ float g_adapt[Nn * Ssub * Vv * Vv];    // [n][s][v][w]
__device__ float g_y[(size_t)Nn * Cc * TV];       // [n][o][t*25+w]
__device__ float g_bn[256];                       // [0:64] sum, [64:128] sumsq, [128:192] scale, [192:256] shift

// -------- kernel 0: zero BN accumulators --------
__global__ void zero_bn_kernel() {
    if (threadIdx.x < 128) g_bn[threadIdx.x] = 0.f;
}

// -------- kernel 1: AB[n] = [wa;wb][96,64] x x[n][64,7500]  (+bias) --------
// grid (59, 64), block 256, dyn smem
__global__ void __launch_bounds__(256) proj_kernel(
    const float* __restrict__ x,
    const float* __restrict__ wa, const float* __restrict__ ba,
    const float* __restrict__ wb, const float* __restrict__ bb)
{
    extern __shared__ float sm[];
    float* Ws   = sm;               // 96*65 (padded)
    float* Bs   = Ws + 96 * 65;     // 64*128
    float* biasS = Bs + 64 * 128;   // 96

    const int n = blockIdx.y;
    const int col0 = blockIdx.x * 128;
    const int tid = threadIdx.x;

    for (int i = tid; i < 96 * 64; i += 256) {
        int r = i >> 6, c = i & 63;
        Ws[r * 65 + c] = (r < 48) ? wa[r * 64 + c] : wb[(r - 48) * 64 + c];
    }
    if (tid < 96) biasS[tid] = (tid < 48) ? ba[tid] : bb[tid - 48];
    for (int i = tid; i < 64 * 128; i += 256) {
        int c = i >> 7, j = i & 127;
        int col = col0 + j;
        Bs[i] = (col < TV) ? x[((size_t)n * Cc + c) * TV + col] : 0.f;
    }
    __syncthreads();

    const int ty = tid >> 4, tx = tid & 15;
    float acc[6][8];
#pragma unroll
    for (int a = 0; a < 6; a++)
#pragma unroll
        for (int b = 0; b < 8; b++) acc[a][b] = 0.f;

    for (int c = 0; c < 64; c++) {
        float wr[6], xr[8];
#pragma unroll
        for (int jm = 0; jm < 6; jm++) wr[jm] = Ws[(ty * 6 + jm) * 65 + c];
#pragma unroll
        for (int jc = 0; jc < 8; jc++) xr[jc] = Bs[c * 128 + tx + 16 * jc];
#pragma unroll
        for (int jm = 0; jm < 6; jm++)
#pragma unroll
            for (int jc = 0; jc < 8; jc++) acc[jm][jc] += wr[jm] * xr[jc];
    }

#pragma unroll
    for (int jm = 0; jm < 6; jm++) {
        int r = ty * 6 + jm;
        size_t base = ((size_t)n * 96 + r) * TV;
        float bias = biasS[r];
#pragma unroll
        for (int jc = 0; jc < 8; jc++) {
            int col = col0 + tx + 16 * jc;
            if (col < TV) g_ab[base + col] = acc[jm][jc] + bias;
        }
    }
}

// -------- kernel 2: scores (K=4800) + softmax(axis=v) + adapt = A+W+attn --------
// grid (3, 64) = (s, n), block 256 (250 active compute threads)
__global__ void __launch_bounds__(256) scores_kernel(
    const float* __restrict__ A, const float* __restrict__ W)
{
    __shared__ float aS[1000];
    __shared__ float bS[1000];
    __shared__ float scS[625];

    const int s = blockIdx.x, n = blockIdx.y;
    const int tid = threadIdx.x;

    for (int i = tid; i < 625; i += 256) scS[i] = 0.f;

    const size_t abase = ((size_t)n * 96 + s * 16) * TV;
    const size_t bbase = ((size_t)n * 96 + 48 + s * 16) * TV;

    const int ks = tid / 25;
    const int rem = tid % 25;
    const int wg = rem / 5, vg = rem % 5;

    float acc[5][5];
#pragma unroll
    for (int a = 0; a < 5; a++)
#pragma unroll
        for (int b = 0; b < 5; b++) acc[a][b] = 0.f;

    for (int st = 0; st < 120; st++) {   // 120 * 40 k-rows = 4800
        __syncthreads();
        for (int i = tid; i < 1000; i += 256) {
            aS[i] = g_ab[abase + (size_t)st * 1000 + i];
            bS[i] = g_ab[bbase + (size_t)st * 1000 + i];
        }
        __syncthreads();
        if (ks < 10) {
#pragma unroll
            for (int j = 0; j < 4; j++) {
                int k = ks * 4 + j;
                float ra[5], rb[5];
#pragma unroll
                for (int iv = 0; iv < 5; iv++) ra[iv] = aS[k * 25 + vg * 5 + iv];
#pragma unroll
                for (int iw = 0; iw < 5; iw++) rb[iw] = bS[k * 25 + wg * 5 + iw];
#pragma unroll
                for (int iv = 0; iv < 5; iv++)
#pragma unroll
                    for (int iw = 0; iw < 5; iw++) acc[iv][iw] += ra[iv] * rb[iw];
            }
        }
    }
    __syncthreads();
    if (ks < 10) {
#pragma unroll
        for (int iv = 0; iv < 5; iv++)
#pragma unroll
            for (int iw = 0; iw < 5; iw++)
                atomicAdd(&scS[(vg * 5 + iv) * 25 + (wg * 5 + iw)], acc[iv][iw]);
    }
    __syncthreads();

    if (tid < 25) {
        const int w = tid;
        const float inv = 1.f / 4800.f;
        float m = -1e30f;
        for (int v = 0; v < 25; v++) m = fmaxf(m, scS[v * 25 + w]);
        m *= inv;
        float sum = 0.f;
        for (int v = 0; v < 25; v++) {
            float ev = expf(scS[v * 25 + w] * inv - m);
            scS[v * 25 + w] = ev;
            sum += ev;
        }
        float rs = 1.f / sum;
        for (int v = 0; v < 25; v++) {
            int widx = (s * 25 + v) * 25 + w;
            g_adapt[((size_t)(n * 3 + s)) * 625 + v * 25 + w] =
                A[widx] + W[widx] + scS[v * 25 + w] * rs;
        }
    }
}

// -------- kernel 3: fused y = sum_s wd[s]^T (x . adapt[s]) + bd, with BN partial sums --------
// grid (59, 64), block 256, dyn smem
__global__ void __launch_bounds__(256) y_kernel(
    const float* __restrict__ x, const float* __restrict__ wd,
    const float* __restrict__ bd)
{
    extern __shared__ float sm[];
    float* tmpS = sm;                 // 64*177 (padded) — doubles as x staging
    float* wdS  = tmpS + 64 * 177;    // 4096
    float* adS  = wdS + 4096;         // 1875
    float* bdS  = adS + 1875;         // 64
    float* bnS  = bdS + 64;           // 128

    const int n = blockIdx.y;
    const int col0 = blockIdx.x * 128;
    const int ncols = min(128, TV - col0);
    const int t0 = col0 / 25;
    const int off0 = col0 - t0 * 25;
    const int tEnd = (col0 + ncols - 1) / 25;
    const int tspan = tEnd - t0 + 1;        // <= 7
    const int X = tspan * 25;

    const int tid = threadIdx.x;
    const int ty = tid >> 4, tx = tid & 15;

    if (tid < 64) bdS[tid] = bd[tid] + bd[64 + tid] + bd[128 + tid];
    if (tid >= 64 && tid < 192) bnS[tid - 64] = 0.f;
    for (int i = tid; i < 1875; i += 256) adS[i] = g_adapt[(size_t)n * 1875 + i];
    for (int i = tid; i < 64 * X; i += 256) {
        int c = i / X, jj = i - c * X;
        tmpS[c * 177 + jj] = x[((size_t)n * Cc + c) * TV + t0 * 25 + jj];
    }
    __syncthreads();

    // cache the x rows this thread owns in registers (<= 2 (c,t) pairs)
    float xv0[25], xv1[25];
    const int P = 64 * tspan;
    const int p0 = tid, p1 = tid + 256;
    if (p0 < P) {
        int tl = p0 / 64, c = p0 % 64;
#pragma unroll
        for (int v = 0; v < 25; v++) xv0[v] = tmpS[c * 177 + tl * 25 + v];
    }
    if (p1 < P) {
        int tl = p1 / 64, c = p1 % 64;
#pragma unroll
        for (int v = 0; v < 25; v++) xv1[v] = tmpS[c * 177 + tl * 25 + v];
    }
    __syncthreads();

    float acc[4][8];
#pragma unroll
    for (int a = 0; a < 4; a++)
#pragma unroll
        for (int b = 0; b < 8; b++) acc[a][b] = 0.f;

    for (int s = 0; s < 3; s++) {
        // load wd[s] (independent smem region) while computing tmp
        for (int i = tid; i < 4096; i += 256) wdS[i] = wd[s * 4096 + i];
        const float* ad = adS + s * 625;
        if (p0 < P) {
            int tl = p0 / 64, c = p0 % 64;
            for (int w = 0; w < 25; w++) {
                float a = 0.f;
#pragma unroll
                for (int v = 0; v < 25; v++) a += xv0[v] * ad[v * 25 + w];
                tmpS[c * 177 + tl * 25 + w] = a;
            }
        }
        if (p1 < P) {
            int tl = p1 / 64, c = p1 % 64;
            for (int w = 0; w < 25; w++) {
                float a = 0.f;
#pragma unroll
                for (int v = 0; v < 25; v++) a += xv1[v] * ad[v * 25 + w];
                tmpS[c * 177 + tl * 25 + w] = a;
            }
        }
        __syncthreads();

        for (int c = 0; c < 64; c++) {
            float wr[4], tr[8];
#pragma unroll
            for (int jo = 0; jo < 4; jo++) wr[jo] = wdS[(ty * 4 + jo) * 64 + c];
#pragma unroll
            for (int jc = 0; jc < 8; jc++) tr[jc] = tmpS[c * 177 + off0 + tx + 16 * jc];
#pragma unroll
            for (int jo = 0; jo < 4; jo++)
#pragma unroll
                for (int jc = 0; jc < 8; jc++) acc[jo][jc] += wr[jo] * tr[jc];
        }
        __syncthreads();
    }

    float s1[4] = {0.f, 0.f, 0.f, 0.f}, s2[4] = {0.f, 0.f, 0.f, 0.f};
#pragma unroll
    for (int jo = 0; jo < 4; jo++) {
        int o = ty * 4 + jo;
        size_t base = ((size_t)n * Cc + o) * TV + col0;
        float bias = bdS[o];
#pragma unroll
        for (int jc = 0; jc < 8; jc++) {
            int col = tx + 16 * jc;
            if (col < ncols) {
                float v = acc[jo][jc] + bias;
                g_y[base + col] = v;
                s1[jo] += v;
                s2[jo] += v * v;
            }
        }
    }
#pragma unroll
    for (int jo = 0; jo < 4; jo++) {
        int o = ty * 4 + jo;
        atomicAdd(&bnS[o], s1[jo]);
        atomicAdd(&bnS[64 + o], s2[jo]);
    }
    __syncthreads();
    if (tid < 128) atomicAdd(&g_bn[tid], bnS[tid]);
}

// -------- kernel 4: finalize BN stats into scale/shift --------
__global__ void bnfinal_kernel(const float* __restrict__ gamma,
                               const float* __restrict__ beta)
{
    int o = threadIdx.x;
    if (o < 64) {
        const float cnt = (float)Nn * (float)TV;  // 480000
        float mean = g_bn[o] / cnt;
        float var = g_bn[64 + o] / cnt - mean * mean;
        float sc = gamma[o] * rsqrtf(var + 1e-5f);
        g_bn[128 + o] = sc;
        g_bn[192 + o] = beta[o] - mean * sc;
    }
}

// -------- kernel 5: out = relu(bn(y) + x), vectorized float4 --------
// 30,720,000 floats = 7,680,000 float4; each row of TV=7500 floats is 1875 float4s.
__global__ void final_kernel(const float* __restrict__ x, float* __restrict__ out)
{
    unsigned idx = blockIdx.x * 256u + threadIdx.x;       // < 7,680,000 (fits u32)
    unsigned row = idx / 1875u;                            // (n*64 + c)
    int c = (int)(row & 63u);
    size_t base = (size_t)idx * 4;
    float sc = g_bn[128 + c], sh = g_bn[192 + c];
    float4 y = *reinterpret_cast<const float4*>(g_y + base);
    float4 xr = *reinterpret_cast<const float4*>(x + base);
    float4 o;
    o.x = fmaxf(y.x * sc + sh + xr.x, 0.f);
    o.y = fmaxf(y.y * sc + sh + xr.y, 0.f);
    o.z = fmaxf(y.z * sc + sh + xr.z, 0.f);
    o.w = fmaxf(y.w * sc + sh + xr.w, 0.f);
    *reinterpret_cast<float4*>(out + base) = o;
}

extern "C" void kernel_launch(void* const* d_in, const int* in_sizes, int n_in,
                              void* d_out, int out_size)
{
    const float* x     = (const float*)d_in[0];
    const float* A     = (const float*)d_in[1];
    const float* W     = (const float*)d_in[2];
    const float* wa    = (const float*)d_in[3];
    const float* ba    = (const float*)d_in[4];
    const float* wb    = (const float*)d_in[5];
    const float* bb    = (const float*)d_in[6];
    const float* wd    = (const float*)d_in[7];
    const float* bd    = (const float*)d_in[8];
    const float* gamma = (const float*)d_in[9];
    const float* beta  = (const float*)d_in[10];
    float* out = (float*)d_out;

    const int PROJ_SMEM = (96 * 65 + 64 * 128 + 96) * 4;                 // 58112 B
    const int Y_SMEM    = (64 * 177 + 4096 + 1875 + 64 + 128) * 4;       // 69964 B
    cudaFuncSetAttribute(proj_kernel, cudaFuncAttributeMaxDynamicSharedMemorySize, PROJ_SMEM);
    cudaFuncSetAttribute(y_kernel,    cudaFuncAttributeMaxDynamicSharedMemorySize, Y_SMEM);

    zero_bn_kernel<<<1, 128>>>();
    proj_kernel<<<dim3(59, 64), 256, PROJ_SMEM>>>(x, wa, ba, wb, bb);
    scores_kernel<<<dim3(3, 64), 256>>>(A, W);
    y_kernel<<<dim3(59, 64), 256, Y_SMEM>>>(x, wd, bd);
    bnfinal_kernel<<<1, 64>>>(gamma, beta);
    final_kernel<<<30000, 256>>>(x, out);
}

// round 5
// speedup vs baseline: 1.3589x; 1.3589x over previous
#include <cuda_runtime.h>

#define Nn 64
#define Cc 64
#define Tt 300
#define Vv 25
#define Ssub 3
#define TV 7500

// -------- scratch (device globals: no allocation allowed) --------
__device__ float g_ab[(size_t)Nn * 96 * TV];      // [n][96 rows: 0-47 = a(s,i), 48-95 = b(s,i)][t*25+v]
__device__ float g_adapt[Nn * Ssub * Vv * Vv];    // [n][s][v][w]
__device__ float g_y[(size_t)Nn * Cc * TV];       // [n][o][t*25+w]
__device__ float g_bn[256];                       // [0:64] sum, [64:128] sumsq, [128:192] scale, [192:256] shift

// -------- kernel 0: zero BN accumulators --------
__global__ void zero_bn_kernel() {
    if (threadIdx.x < 128) g_bn[threadIdx.x] = 0.f;
}

// -------- kernel 1: AB[n] = [wa;wb][96,64] x x[n][64,7500]  (+bias) --------
__global__ void __launch_bounds__(256) proj_kernel(
    const float* __restrict__ x,
    const float* __restrict__ wa, const float* __restrict__ ba,
    const float* __restrict__ wb, const float* __restrict__ bb)
{
    extern __shared__ float sm[];
    float* Ws   = sm;               // 96*65 (padded)
    float* Bs   = Ws + 96 * 65;     // 64*128
    float* biasS = Bs + 64 * 128;   // 96

    const int n = blockIdx.y;
    const int col0 = blockIdx.x * 128;
    const int tid = threadIdx.x;

    for (int i = tid; i < 96 * 64; i += 256) {
        int r = i >> 6, c = i & 63;
        Ws[r * 65 + c] = (r < 48) ? wa[r * 64 + c] : wb[(r - 48) * 64 + c];
    }
    if (tid < 96) biasS[tid] = (tid < 48) ? ba[tid] : bb[tid - 48];
    for (int i = tid; i < 64 * 128; i += 256) {
        int c = i >> 7, j = i & 127;
        int col = col0 + j;
        Bs[i] = (col < TV) ? x[((size_t)n * Cc + c) * TV + col] : 0.f;
    }
    __syncthreads();

    const int ty = tid >> 4, tx = tid & 15;
    float acc[6][8];
#pragma unroll
    for (int a = 0; a < 6; a++)
#pragma unroll
        for (int b = 0; b < 8; b++) acc[a][b] = 0.f;

    for (int c = 0; c < 64; c++) {
        float wr[6], xr[8];
#pragma unroll
        for (int jm = 0; jm < 6; jm++) wr[jm] = Ws[(ty * 6 + jm) * 65 + c];
#pragma unroll
        for (int jc = 0; jc < 8; jc++) xr[jc] = Bs[c * 128 + tx + 16 * jc];
#pragma unroll
        for (int jm = 0; jm < 6; jm++)
#pragma unroll
            for (int jc = 0; jc < 8; jc++) acc[jm][jc] += wr[jm] * xr[jc];
    }

#pragma unroll
    for (int jm = 0; jm < 6; jm++) {
        int r = ty * 6 + jm;
        size_t base = ((size_t)n * 96 + r) * TV;
        float bias = biasS[r];
#pragma unroll
        for (int jc = 0; jc < 8; jc++) {
            int col = col0 + tx + 16 * jc;
            if (col < TV) g_ab[base + col] = acc[jm][jc] + bias;
        }
    }
}

// -------- kernel 2: scores (K=4800) + softmax(axis=v) + adapt = A+W+attn --------
__global__ void __launch_bounds__(256) scores_kernel(
    const float* __restrict__ A, const float* __restrict__ W)
{
    __shared__ float aS[1000];
    __shared__ float bS[1000];
    __shared__ float scS[625];

    const int s = blockIdx.x, n = blockIdx.y;
    const int tid = threadIdx.x;

    for (int i = tid; i < 625; i += 256) scS[i] = 0.f;

    const size_t abase = ((size_t)n * 96 + s * 16) * TV;
    const size_t bbase = ((size_t)n * 96 + 48 + s * 16) * TV;

    const int ks = tid / 25;
    const int rem = tid % 25;
    const int wg = rem / 5, vg = rem % 5;

    float acc[5][5];
#pragma unroll
    for (int a = 0; a < 5; a++)
#pragma unroll
        for (int b = 0; b < 5; b++) acc[a][b] = 0.f;

    float4* aS4 = reinterpret_cast<float4*>(aS);
    float4* bS4 = reinterpret_cast<float4*>(bS);

    for (int st = 0; st < 120; st++) {   // 120 * 40 k-rows = 4800
        __syncthreads();
        // 1000 floats = 250 float4 per buffer; slabs are contiguous & 16B-aligned
        if (tid < 250) {
            const float4* ga = reinterpret_cast<const float4*>(g_ab + abase + (size_t)st * 1000);
            const float4* gb = reinterpret_cast<const float4*>(g_ab + bbase + (size_t)st * 1000);
            aS4[tid] = ga[tid];
            bS4[tid] = gb[tid];
        }
        __syncthreads();
        if (ks < 10) {
#pragma unroll
            for (int j = 0; j < 4; j++) {
                int k = ks * 4 + j;
                float ra[5], rb[5];
#pragma unroll
                for (int iv = 0; iv < 5; iv++) ra[iv] = aS[k * 25 + vg * 5 + iv];
#pragma unroll
                for (int iw = 0; iw < 5; iw++) rb[iw] = bS[k * 25 + wg * 5 + iw];
#pragma unroll
                for (int iv = 0; iv < 5; iv++)
#pragma unroll
                    for (int iw = 0; iw < 5; iw++) acc[iv][iw] += ra[iv] * rb[iw];
            }
        }
    }
    __syncthreads();
    if (ks < 10) {
#pragma unroll
        for (int iv = 0; iv < 5; iv++)
#pragma unroll
            for (int iw = 0; iw < 5; iw++)
                atomicAdd(&scS[(vg * 5 + iv) * 25 + (wg * 5 + iw)], acc[iv][iw]);
    }
    __syncthreads();

    if (tid < 25) {
        const int w = tid;
        const float inv = 1.f / 4800.f;
        float m = -1e30f;
        for (int v = 0; v < 25; v++) m = fmaxf(m, scS[v * 25 + w]);
        m *= inv;
        float sum = 0.f;
        for (int v = 0; v < 25; v++) {
            float ev = expf(scS[v * 25 + w] * inv - m);
            scS[v * 25 + w] = ev;
            sum += ev;
        }
        float rs = 1.f / sum;
        for (int v = 0; v < 25; v++) {
            int widx = (s * 25 + v) * 25 + w;
            g_adapt[((size_t)(n * 3 + s)) * 625 + v * 25 + w] =
                A[widx] + W[widx] + scS[v * 25 + w] * rs;
        }
    }
}

// -------- kernel 3: fused y = sum_s wd[s]^T (x . adapt[s]) + bd, with BN partial sums --------
// grid (59, 64), block 256, dyn smem
// smem: tmpS 64*177, wdT 64*68 (transposed, padded), adS 3*700 (rows padded to 28, zero-filled)
__global__ void __launch_bounds__(256) y_kernel(
    const float* __restrict__ x, const float* __restrict__ wd,
    const float* __restrict__ bd)
{
    extern __shared__ float sm[];
    float* tmpS = sm;                 // 64*177 — doubles as x staging
    float* wdT  = tmpS + 64 * 177;    // 64*68, wdT[c*68+o] = wd[s][o][c]
    float* adS  = wdT + 64 * 68;      // 3*700, adS[s*700 + v*28 + w], w>=25 zero
    float* bdS  = adS + 2100;         // 64
    float* bnS  = bdS + 64;           // 128

    const int n = blockIdx.y;
    const int col0 = blockIdx.x * 128;
    const int ncols = min(128, TV - col0);
    const int t0 = col0 / 25;
    const int off0 = col0 - t0 * 25;
    const int tEnd = (col0 + ncols - 1) / 25;
    const int tspan = tEnd - t0 + 1;        // <= 7
    const int X = tspan * 25;

    const int tid = threadIdx.x;
    const int ty = tid >> 4, tx = tid & 15;

    if (tid < 64) bdS[tid] = bd[tid] + bd[64 + tid] + bd[128 + tid];
    if (tid >= 64 && tid < 192) bnS[tid - 64] = 0.f;
    for (int i = tid; i < 2100; i += 256) {
        int si = i / 700, r = i - si * 700;
        int v = r / 28, w = r - v * 28;
        adS[i] = (w < 25) ? g_adapt[(size_t)n * 1875 + si * 625 + v * 25 + w] : 0.f;
    }
    for (int i = tid; i < 64 * X; i += 256) {
        int c = i / X, jj = i - c * X;
        tmpS[c * 177 + jj] = x[((size_t)n * Cc + c) * TV + t0 * 25 + jj];
    }
    __syncthreads();

    // cache the x rows this thread owns in registers (<= 2 (c,t) pairs)
    float xv0[25], xv1[25];
    const int P = 64 * tspan;
    const int p0 = tid, p1 = tid + 256;
    if (p0 < P) {
        int tl = p0 / 64, c = p0 % 64;
#pragma unroll
        for (int v = 0; v < 25; v++) xv0[v] = tmpS[c * 177 + tl * 25 + v];
    }
    if (p1 < P) {
        int tl = p1 / 64, c = p1 % 64;
#pragma unroll
        for (int v = 0; v < 25; v++) xv1[v] = tmpS[c * 177 + tl * 25 + v];
    }
    __syncthreads();

    float acc[4][8];
#pragma unroll
    for (int a = 0; a < 4; a++)
#pragma unroll
        for (int b = 0; b < 8; b++) acc[a][b] = 0.f;

    for (int s = 0; s < 3; s++) {
        // load wd[s] transposed (independent smem region) while computing tmp
        for (int i = tid; i < 4096; i += 256) {
            int o = i >> 6, c = i & 63;
            wdT[c * 68 + o] = wd[s * 4096 + i];
        }
        const float* ad = adS + s * 700;
        // tmp[c, tl*25+w] = sum_v xv[v] * adapt[v][w], float4 adapt loads
        if (p0 < P) {
            int tl = p0 / 64, c = p0 % 64;
            float a28[28];
#pragma unroll
            for (int i = 0; i < 28; i++) a28[i] = 0.f;
            for (int v = 0; v < 25; v++) {
                float xr = xv0[v];
                const float4* a4 = reinterpret_cast<const float4*>(ad + v * 28);
#pragma unroll
                for (int w4 = 0; w4 < 7; w4++) {
                    float4 t = a4[w4];
                    a28[w4 * 4 + 0] += xr * t.x;
                    a28[w4 * 4 + 1] += xr * t.y;
                    a28[w4 * 4 + 2] += xr * t.z;
                    a28[w4 * 4 + 3] += xr * t.w;
                }
            }
#pragma unroll
            for (int w = 0; w < 25; w++) tmpS[c * 177 + tl * 25 + w] = a28[w];
        }
        if (p1 < P) {
            int tl = p1 / 64, c = p1 % 64;
            float a28[28];
#pragma unroll
            for (int i = 0; i < 28; i++) a28[i] = 0.f;
            for (int v = 0; v < 25; v++) {
                float xr = xv1[v];
                const float4* a4 = reinterpret_cast<const float4*>(ad + v * 28);
#pragma unroll
                for (int w4 = 0; w4 < 7; w4++) {
                    float4 t = a4[w4];
                    a28[w4 * 4 + 0] += xr * t.x;
                    a28[w4 * 4 + 1] += xr * t.y;
                    a28[w4 * 4 + 2] += xr * t.z;
                    a28[w4 * 4 + 3] += xr * t.w;
                }
            }
#pragma unroll
            for (int w = 0; w < 25; w++) tmpS[c * 177 + tl * 25 + w] = a28[w];
        }
        __syncthreads();

        for (int c = 0; c < 64; c++) {
            float4 w4 = *reinterpret_cast<const float4*>(wdT + c * 68 + ty * 4);
            float wr[4] = {w4.x, w4.y, w4.z, w4.w};
            float tr[8];
#pragma unroll
            for (int jc = 0; jc < 8; jc++) tr[jc] = tmpS[c * 177 + off0 + tx + 16 * jc];
#pragma unroll
            for (int jo = 0; jo < 4; jo++)
#pragma unroll
                for (int jc = 0; jc < 8; jc++) acc[jo][jc] += wr[jo] * tr[jc];
        }
        __syncthreads();
    }

    float s1[4] = {0.f, 0.f, 0.f, 0.f}, s2[4] = {0.f, 0.f, 0.f, 0.f};
#pragma unroll
    for (int jo = 0; jo < 4; jo++) {
        int o = ty * 4 + jo;
        size_t base = ((size_t)n * Cc + o) * TV + col0;
        float bias = bdS[o];
#pragma unroll
        for (int jc = 0; jc < 8; jc++) {
            int col = tx + 16 * jc;
            if (col < ncols) {
                float v = acc[jo][jc] + bias;
                g_y[base + col] = v;
                s1[jo] += v;
                s2[jo] += v * v;
            }
        }
    }
#pragma unroll
    for (int jo = 0; jo < 4; jo++) {
        int o = ty * 4 + jo;
        atomicAdd(&bnS[o], s1[jo]);
        atomicAdd(&bnS[64 + o], s2[jo]);
    }
    __syncthreads();
    if (tid < 128) atomicAdd(&g_bn[tid], bnS[tid]);
}

// -------- kernel 4: finalize BN stats into scale/shift --------
__global__ void bnfinal_kernel(const float* __restrict__ gamma,
                               const float* __restrict__ beta)
{
    int o = threadIdx.x;
    if (o < 64) {
        const float cnt = (float)Nn * (float)TV;  // 480000
        float mean = g_bn[o] / cnt;
        float var = g_bn[64 + o] / cnt - mean * mean;
        float sc = gamma[o] * rsqrtf(var + 1e-5f);
        g_bn[128 + o] = sc;
        g_bn[192 + o] = beta[o] - mean * sc;
    }
}

// -------- kernel 5: out = relu(bn(y) + x), vectorized float4 --------
__global__ void final_kernel(const float* __restrict__ x, float* __restrict__ out)
{
    unsigned idx = blockIdx.x * 256u + threadIdx.x;       // < 7,680,000 (fits u32)
    unsigned row = idx / 1875u;                            // (n*64 + c)
    int c = (int)(row & 63u);
    size_t base = (size_t)idx * 4;
    float sc = g_bn[128 + c], sh = g_bn[192 + c];
    float4 y = *reinterpret_cast<const float4*>(g_y + base);
    float4 xr = *reinterpret_cast<const float4*>(x + base);
    float4 o;
    o.x = fmaxf(y.x * sc + sh + xr.x, 0.f);
    o.y = fmaxf(y.y * sc + sh + xr.y, 0.f);
    o.z = fmaxf(y.z * sc + sh + xr.z, 0.f);
    o.w = fmaxf(y.w * sc + sh + xr.w, 0.f);
    *reinterpret_cast<float4*>(out + base) = o;
}

extern "C" void kernel_launch(void* const* d_in, const int* in_sizes, int n_in,
                              void* d_out, int out_size)
{
    const float* x     = (const float*)d_in[0];
    const float* A     = (const float*)d_in[1];
    const float* W     = (const float*)d_in[2];
    const float* wa    = (const float*)d_in[3];
    const float* ba    = (const float*)d_in[4];
    const float* wb    = (const float*)d_in[5];
    const float* bb    = (const float*)d_in[6];
    const float* wd    = (const float*)d_in[7];
    const float* bd    = (const float*)d_in[8];
    const float* gamma = (const float*)d_in[9];
    const float* beta  = (const float*)d_in[10];
    float* out = (float*)d_out;

    const int PROJ_SMEM = (96 * 65 + 64 * 128 + 96) * 4;                       // 58112 B
    const int Y_SMEM    = (64 * 177 + 64 * 68 + 2100 + 64 + 128) * 4;          // 71888 B
    cudaFuncSetAttribute(proj_kernel, cudaFuncAttributeMaxDynamicSharedMemorySize, PROJ_SMEM);
    cudaFuncSetAttribute(y_kernel,    cudaFuncAttributeMaxDynamicSharedMemorySize, Y_SMEM);

    zero_bn_kernel<<<1, 128>>>();
    proj_kernel<<<dim3(59, 64), 256, PROJ_SMEM>>>(x, wa, ba, wb, bb);
    scores_kernel<<<dim3(3, 64), 256>>>(A, W);
    y_kernel<<<dim3(59, 64), 256, Y_SMEM>>>(x, wd, bd);
    bnfinal_kernel<<<1, 64>>>(gamma, beta);
    final_kernel<<<30000, 256>>>(x, out);
}